// round 8
// baseline (speedup 1.0000x reference)
#include <cuda_runtime.h>
#include <cuda_bf16.h>
#include <math.h>

#define N_NODES 100000
#define E_EDGES 3200000
#define F_IN    256
#define F_HID   16
#define F_OUT   40

#define PREP_BLOCKS  148
#define PREP_THREADS 1024
#define SCAN_BS 1024
#define SCAN_NB ((N_NODES + SCAN_BS - 1) / SCAN_BS)   // 98

// -------- scratch (static device globals; 16B-aligned) ----------------------
__device__ __align__(16) float g_deg   [N_NODES];
__device__ __align__(16) float g_dinv  [N_NODES];
__device__ __align__(16) float g_h1    [N_NODES * F_HID];
__device__ __align__(16) float g_agg1  [N_NODES * F_HID];
__device__ __align__(16) int   g_row   [E_EDGES];
__device__ __align__(16) int   g_col   [E_EDGES];
__device__ __align__(16) int   g_cnt   [N_NODES];
__device__ __align__(16) int   g_ptr   [N_NODES + 1];
__device__ __align__(16) int   g_cursor[N_NODES];
__device__ __align__(16) int2  g_sedge [E_EDGES];      // {row, bits(norm)}
__device__ __align__(16) int   g_bsum  [SCAN_NB];
__device__ __align__(16) int   g_boff  [SCAN_NB];
__device__ int g_idx32 = 0;   // 1 => edge_index is int32, 0 => int64

// grid barrier state (generation counter: correct across graph replays)
__device__ unsigned g_bar_count = 0;
__device__ volatile unsigned g_bar_gen = 0;

__device__ __forceinline__ void gbar(unsigned& mygen) {
    __syncthreads();
    if (threadIdx.x == 0) {
        __threadfence();
        unsigned target = mygen + 1;
        if (atomicAdd(&g_bar_count, 1u) == (unsigned)(gridDim.x - 1)) {
            g_bar_count = 0;
            __threadfence();
            g_bar_gen = target;
        } else {
            while (g_bar_gen < target) { __nanosleep(64); }
        }
        mygen = target;
    }
    __syncthreads();
    __threadfence();
}

// ---------------------------------------------------------------------------
// persistent preprocessing kernel: detect, degree, dinv, scan, CSR fill
// ---------------------------------------------------------------------------
__global__ void __launch_bounds__(PREP_THREADS, 1)
k_prep(const void* __restrict__ ei, const float* __restrict__ ew) {
    __shared__ int s_scan[SCAN_BS];
    __shared__ int s_or[32];

    const int tid = threadIdx.x;
    const int bid = blockIdx.x;
    const int gtid = bid * PREP_THREADS + tid;
    const int nth  = PREP_BLOCKS * PREP_THREADS;

    unsigned mygen = 0;
    if (tid == 0) mygen = g_bar_gen;

    // ---- P1: node init + dtype detection (block 0) ----
    for (int i = gtid; i < N_NODES; i += nth) { g_deg[i] = 1.0f; g_cnt[i] = 0; }
    if (bid == 0) {
        int bad = 0;
#pragma unroll
        for (int q = 0; q < 4; q++) {
            long long v = ((const long long*)ei)[tid + q * 1024];
            if (v < 0 || v >= N_NODES) bad = 1;
        }
        bad = __any_sync(0xffffffffu, bad) ? 1 : 0;
        if ((tid & 31) == 0) s_or[tid >> 5] = bad;
        __syncthreads();
        if (tid == 0) {
            int r = 0;
            for (int w = 0; w < 32; w++) r |= s_or[w];
            g_idx32 = r;
        }
    }
    gbar(mygen);

    // ---- P2: edge decode + degree/count histogram ----
    {
        const int idx32 = g_idx32;
        if (idx32) {
            const int* e32 = (const int*)ei;
            for (int e = gtid; e < E_EDGES; e += nth) {
                int row = e32[e];
                int col = e32[E_EDGES + e];
                if ((unsigned)row >= (unsigned)N_NODES) row = 0;
                if ((unsigned)col >= (unsigned)N_NODES) col = 0;
                g_row[e] = row; g_col[e] = col;
                atomicAdd(&g_deg[col], ew[e]);
                atomicAdd(&g_cnt[col], 1);
            }
        } else {
            const long long* e64 = (const long long*)ei;
            for (int e = gtid; e < E_EDGES; e += nth) {
                int row = (int)e64[e];
                int col = (int)e64[E_EDGES + e];
                if ((unsigned)row >= (unsigned)N_NODES) row = 0;
                if ((unsigned)col >= (unsigned)N_NODES) col = 0;
                g_row[e] = row; g_col[e] = col;
                atomicAdd(&g_deg[col], ew[e]);
                atomicAdd(&g_cnt[col], 1);
            }
        }
    }
    gbar(mygen);

    // ---- P3: dinv (all blocks) + per-chunk scan (blocks 0..SCAN_NB-1) ----
    for (int i = gtid; i < N_NODES; i += nth) {
        float d = g_deg[i];
        g_dinv[i] = (d > 0.0f) ? rsqrtf(d) : 0.0f;
    }
    if (bid < SCAN_NB) {
        int i = bid * SCAN_BS + tid;
        int v = (i < N_NODES) ? g_cnt[i] : 0;
        s_scan[tid] = v;
        __syncthreads();
#pragma unroll
        for (int off = 1; off < SCAN_BS; off <<= 1) {
            int t = (tid >= off) ? s_scan[tid - off] : 0;
            __syncthreads();
            s_scan[tid] += t;
            __syncthreads();
        }
        if (i < N_NODES) g_ptr[i] = s_scan[tid] - v;   // exclusive within chunk
        if (tid == SCAN_BS - 1) g_bsum[bid] = s_scan[SCAN_BS - 1];
    }
    gbar(mygen);

    // ---- P4: scan of chunk sums (block 0) ----
    if (bid == 0) {
        if (tid < SCAN_NB) s_scan[tid] = g_bsum[tid];
        __syncthreads();
        if (tid == 0) {
            int run = 0;
            for (int b = 0; b < SCAN_NB; b++) {
                g_boff[b] = run;
                run += s_scan[b];
            }
        }
    }
    gbar(mygen);

    // ---- P5: add chunk offsets; init cursors ----
    for (int i = gtid; i < N_NODES; i += nth) {
        int p = g_ptr[i] + g_boff[i >> 10];
        g_ptr[i] = p;
        g_cursor[i] = p;
    }
    if (gtid == 0) g_ptr[N_NODES] = E_EDGES;
    gbar(mygen);

    // ---- P6: CSR fill, packed (row, norm), sorted by col ----
    for (int e = gtid; e < E_EDGES; e += nth) {
        int row = g_row[e];
        int col = g_col[e];
        float norm = g_dinv[row] * ew[e] * g_dinv[col];
        int pos = atomicAdd(&g_cursor[col], 1);
        g_sedge[pos] = make_int2(row, __float_as_int(norm));
    }
}

// ---------------------------------------------------------------------------
// h1 = x @ W1 (thread-per-node, W1 in smem)
// ---------------------------------------------------------------------------
__global__ void k_gemm1(const float* __restrict__ x,
                        const float* __restrict__ W1) {
    __shared__ float sW[F_IN * F_HID];   // 16 KB
    for (int i = threadIdx.x; i < F_IN * F_HID; i += blockDim.x)
        sW[i] = W1[i];
    __syncthreads();

    int node = blockIdx.x * blockDim.x + threadIdx.x;
    if (node >= N_NODES) return;

    float acc[F_HID];
#pragma unroll
    for (int f = 0; f < F_HID; f++) acc[f] = 0.0f;

    const float4* xr = reinterpret_cast<const float4*>(x + (size_t)node * F_IN);
#pragma unroll 4
    for (int k4 = 0; k4 < F_IN / 4; k4++) {
        float4 xv = xr[k4];
        int kb = k4 * 4;
#pragma unroll
        for (int f = 0; f < F_HID; f++) {
            acc[f] = fmaf(xv.x, sW[(kb + 0) * F_HID + f], acc[f]);
            acc[f] = fmaf(xv.y, sW[(kb + 1) * F_HID + f], acc[f]);
            acc[f] = fmaf(xv.z, sW[(kb + 2) * F_HID + f], acc[f]);
            acc[f] = fmaf(xv.w, sW[(kb + 3) * F_HID + f], acc[f]);
        }
    }

    float4* h1o = reinterpret_cast<float4*>(g_h1 + (size_t)node * F_HID);
#pragma unroll
    for (int q = 0; q < F_HID / 4; q++)
        h1o[q] = make_float4(acc[q*4+0], acc[q*4+1], acc[q*4+2], acc[q*4+3]);
}

// ---------------------------------------------------------------------------
// layer-1 aggregation (pull gather, half-warp per node)
// agg1[n] = h1[n]*dinv^2 + sum_in h1[row]*norm
// ---------------------------------------------------------------------------
__global__ void k_gather0() {
    int node = blockIdx.x * 16 + (threadIdx.x >> 4);
    int f    = threadIdx.x & 15;

    float di   = g_dinv[node];
    float acc  = g_h1[(size_t)node * F_HID + f] * di * di;

    int start = g_ptr[node];
    int end   = g_ptr[node + 1];
#pragma unroll 4
    for (int i = start; i < end; i++) {
        int2 e = g_sedge[i];
        acc = fmaf(g_h1[(size_t)e.x * F_HID + f], __int_as_float(e.y), acc);
    }
    g_agg1[(size_t)node * F_HID + f] = acc;
}

// ---------------------------------------------------------------------------
// layer-2 aggregation fused with out-projection + log_softmax.
// half-warp per node: 16 lanes hold the 16 hidden features; width-16
// shuffles broadcast features for the 16x40 projection, width-16
// reductions compute log_softmax; direct store to out.
// ---------------------------------------------------------------------------
__global__ void k_gather1_final(const float* __restrict__ b1,
                                const float* __restrict__ W2,
                                const float* __restrict__ b2,
                                float* __restrict__ out) {
    __shared__ float sW[F_HID * F_OUT];
    __shared__ float sb[F_OUT];
    for (int i = threadIdx.x; i < F_HID * F_OUT; i += blockDim.x) sW[i] = W2[i];
    for (int i = threadIdx.x; i < F_OUT; i += blockDim.x) sb[i] = b2[i];
    __syncthreads();

    int node = blockIdx.x * 16 + (threadIdx.x >> 4);
    int f    = threadIdx.x & 15;

    float bf = b1[f];
    float di = g_dinv[node];
    float self = fmaxf(g_agg1[(size_t)node * F_HID + f] + bf, 0.0f);
    float acc = self * di * di;

    int start = g_ptr[node];
    int end   = g_ptr[node + 1];
#pragma unroll 4
    for (int i = start; i < end; i++) {
        int2 e = g_sedge[i];
        float v = fmaxf(g_agg1[(size_t)e.x * F_HID + f] + bf, 0.0f);
        acc = fmaf(v, __int_as_float(e.y), acc);
    }
    // acc == agg2 feature f of this node

    // projection: lane f handles output cols f, f+16, (f+32 if f<8)
    float z0 = sb[f], z1 = sb[f + 16], z2 = (f < 8) ? sb[f + 32] : 0.0f;
#pragma unroll
    for (int k = 0; k < F_HID; k++) {
        float ak = __shfl_sync(0xffffffffu, acc, k, 16);
        z0 = fmaf(ak, sW[k * F_OUT + f],      z0);
        z1 = fmaf(ak, sW[k * F_OUT + f + 16], z1);
        if (f < 8) z2 = fmaf(ak, sW[k * F_OUT + f + 32], z2);
    }

    // log_softmax over 40 cols (width-16 reductions)
    float m = fmaxf(z0, z1);
    if (f < 8) m = fmaxf(m, z2);
#pragma unroll
    for (int o = 8; o > 0; o >>= 1)
        m = fmaxf(m, __shfl_xor_sync(0xffffffffu, m, o, 16));
    float s = expf(z0 - m) + expf(z1 - m) + ((f < 8) ? expf(z2 - m) : 0.0f);
#pragma unroll
    for (int o = 8; o > 0; o >>= 1)
        s += __shfl_xor_sync(0xffffffffu, s, o, 16);
    float lse = m + logf(s);

    float* op = out + (size_t)node * F_OUT;
    op[f]      = z0 - lse;
    op[f + 16] = z1 - lse;
    if (f < 8) op[f + 32] = z2 - lse;
}

// ---------------------------------------------------------------------------
// launch — 4 kernels total
// ---------------------------------------------------------------------------
extern "C" void kernel_launch(void* const* d_in, const int* in_sizes, int n_in,
                              void* d_out, int out_size) {
    const float* x  = nullptr;
    const void*  ei = nullptr;
    const float* ew = nullptr;
    const float* W1 = nullptr;
    const float* b1 = nullptr;
    const float* W2 = nullptr;
    const float* b2 = nullptr;

    for (int i = 0; i < n_in; i++) {
        switch (in_sizes[i]) {
            case N_NODES * F_IN:   x  = (const float*)d_in[i]; break;
            case 2 * E_EDGES:      ei = d_in[i];               break;
            case E_EDGES:          ew = (const float*)d_in[i]; break;
            case F_IN * F_HID:     W1 = (const float*)d_in[i]; break;
            case F_HID:            b1 = (const float*)d_in[i]; break;
            case F_HID * F_OUT:    W2 = (const float*)d_in[i]; break;
            case F_OUT:            b2 = (const float*)d_in[i]; break;
            default: break;
        }
    }
    float* out = (float*)d_out;

    k_prep<<<PREP_BLOCKS, PREP_THREADS>>>(ei, ew);
    k_gemm1<<<(N_NODES + 127) / 128, 128>>>(x, W1);
    k_gather0<<<N_NODES / 16, 256>>>();
    k_gather1_final<<<N_NODES / 16, 256>>>(b1, W2, b2, out);
}

// round 11
// speedup vs baseline: 1.0535x; 1.0535x over previous
#include <cuda_runtime.h>
#include <cuda_bf16.h>
#include <math.h>

#define N_NODES 100000
#define E_EDGES 3200000
#define F_IN    256
#define F_HID   16
#define F_OUT   40

#define PREP_BLOCKS  148
#define PREP_THREADS 1024
#define SCAN_BS 1024
#define SCAN_NB ((N_NODES + SCAN_BS - 1) / SCAN_BS)   // 98

// -------- scratch (static device globals; 16B-aligned) ----------------------
__device__ __align__(16) float g_deg   [N_NODES];
__device__ __align__(16) float g_dinv  [N_NODES];
__device__ __align__(16) float g_h1    [N_NODES * F_HID];
__device__ __align__(16) float g_r1    [N_NODES * F_HID];
__device__ __align__(16) int   g_row   [E_EDGES];
__device__ __align__(16) int   g_col   [E_EDGES];
__device__ __align__(16) int   g_cnt   [N_NODES];
__device__ __align__(16) int   g_ptr   [N_NODES + 1];
__device__ __align__(16) int   g_cursor[N_NODES];
__device__ __align__(16) int2  g_sedge [E_EDGES];      // {row, bits(norm)}
__device__ __align__(16) int   g_bsum  [SCAN_NB];
__device__ __align__(16) int   g_boff  [SCAN_NB];
__device__ int g_idx32 = 0;   // 1 => edge_index is int32, 0 => int64

// grid barrier (generation counter: correct across graph replays)
__device__ unsigned g_bar_count = 0;
__device__ volatile unsigned g_bar_gen = 0;

__device__ __forceinline__ void gbar(unsigned& mygen) {
    __syncthreads();
    if (threadIdx.x == 0) {
        __threadfence();
        unsigned target = mygen + 1;
        if (atomicAdd(&g_bar_count, 1u) == (unsigned)(gridDim.x - 1)) {
            g_bar_count = 0;
            __threadfence();
            g_bar_gen = target;
        } else {
            while (g_bar_gen < target) { __nanosleep(64); }
        }
        mygen = target;
    }
    __syncthreads();
    __threadfence();
}

// ---------------------------------------------------------------------------
// persistent preprocessing kernel: detect, degree, dinv, scan, CSR fill
// ---------------------------------------------------------------------------
__global__ void __launch_bounds__(PREP_THREADS, 1)
k_prep(const void* __restrict__ ei, const float* __restrict__ ew) {
    __shared__ int s_scan[SCAN_BS];
    __shared__ int s_or[32];

    const int tid = threadIdx.x;
    const int bid = blockIdx.x;
    const int gtid = bid * PREP_THREADS + tid;
    const int nth  = PREP_BLOCKS * PREP_THREADS;

    unsigned mygen = 0;
    if (tid == 0) mygen = g_bar_gen;

    // ---- P1: node init + dtype detection (block 0) ----
    for (int i = gtid; i < N_NODES; i += nth) { g_deg[i] = 1.0f; g_cnt[i] = 0; }
    if (bid == 0) {
        int bad = 0;
#pragma unroll
        for (int q = 0; q < 4; q++) {
            long long v = ((const long long*)ei)[tid + q * 1024];
            if (v < 0 || v >= N_NODES) bad = 1;
        }
        bad = __any_sync(0xffffffffu, bad) ? 1 : 0;
        if ((tid & 31) == 0) s_or[tid >> 5] = bad;
        __syncthreads();
        if (tid == 0) {
            int r = 0;
            for (int w = 0; w < 32; w++) r |= s_or[w];
            g_idx32 = r;
        }
    }
    gbar(mygen);

    // ---- P2: edge decode + degree/count histogram ----
    {
        if (g_idx32) {
            const int* e32 = (const int*)ei;
            for (int e = gtid; e < E_EDGES; e += nth) {
                int row = e32[e];
                int col = e32[E_EDGES + e];
                if ((unsigned)row >= (unsigned)N_NODES) row = 0;
                if ((unsigned)col >= (unsigned)N_NODES) col = 0;
                g_row[e] = row; g_col[e] = col;
                atomicAdd(&g_deg[col], ew[e]);
                atomicAdd(&g_cnt[col], 1);
            }
        } else {
            const long long* e64 = (const long long*)ei;
            for (int e = gtid; e < E_EDGES; e += nth) {
                int row = (int)e64[e];
                int col = (int)e64[E_EDGES + e];
                if ((unsigned)row >= (unsigned)N_NODES) row = 0;
                if ((unsigned)col >= (unsigned)N_NODES) col = 0;
                g_row[e] = row; g_col[e] = col;
                atomicAdd(&g_deg[col], ew[e]);
                atomicAdd(&g_cnt[col], 1);
            }
        }
    }
    gbar(mygen);

    // ---- P3: dinv (all blocks) + per-chunk scan (blocks 0..SCAN_NB-1) ----
    for (int i = gtid; i < N_NODES; i += nth) {
        float d = g_deg[i];
        g_dinv[i] = (d > 0.0f) ? rsqrtf(d) : 0.0f;
    }
    if (bid < SCAN_NB) {
        int i = bid * SCAN_BS + tid;
        int v = (i < N_NODES) ? g_cnt[i] : 0;
        s_scan[tid] = v;
        __syncthreads();
#pragma unroll
        for (int off = 1; off < SCAN_BS; off <<= 1) {
            int t = (tid >= off) ? s_scan[tid - off] : 0;
            __syncthreads();
            s_scan[tid] += t;
            __syncthreads();
        }
        if (i < N_NODES) g_ptr[i] = s_scan[tid] - v;   // exclusive within chunk
        if (tid == SCAN_BS - 1) g_bsum[bid] = s_scan[SCAN_BS - 1];
    }
    gbar(mygen);

    // ---- P4: scan of chunk sums (block 0) ----
    if (bid == 0) {
        if (tid < SCAN_NB) s_scan[tid] = g_bsum[tid];
        __syncthreads();
        if (tid == 0) {
            int run = 0;
            for (int b = 0; b < SCAN_NB; b++) {
                g_boff[b] = run;
                run += s_scan[b];
            }
        }
    }
    gbar(mygen);

    // ---- P5: add chunk offsets; init cursors ----
    for (int i = gtid; i < N_NODES; i += nth) {
        int p = g_ptr[i] + g_boff[i >> 10];
        g_ptr[i] = p;
        g_cursor[i] = p;
    }
    if (gtid == 0) g_ptr[N_NODES] = E_EDGES;
    gbar(mygen);

    // ---- P6: CSR fill, packed (row, norm), sorted by col ----
    for (int e = gtid; e < E_EDGES; e += nth) {
        int row = g_row[e];
        int col = g_col[e];
        float norm = g_dinv[row] * ew[e] * g_dinv[col];
        int pos = atomicAdd(&g_cursor[col], 1);
        g_sedge[pos] = make_int2(row, __float_as_int(norm));
    }
}

// ---------------------------------------------------------------------------
// h1 = x @ W1 (thread-per-node, W1 in smem)
// ---------------------------------------------------------------------------
__global__ void k_gemm1(const float* __restrict__ x,
                        const float* __restrict__ W1) {
    __shared__ float sW[F_IN * F_HID];   // 16 KB
    for (int i = threadIdx.x; i < F_IN * F_HID; i += blockDim.x)
        sW[i] = W1[i];
    __syncthreads();

    int node = blockIdx.x * blockDim.x + threadIdx.x;
    if (node >= N_NODES) return;

    float acc[F_HID];
#pragma unroll
    for (int f = 0; f < F_HID; f++) acc[f] = 0.0f;

    const float4* xr = reinterpret_cast<const float4*>(x + (size_t)node * F_IN);
#pragma unroll 4
    for (int k4 = 0; k4 < F_IN / 4; k4++) {
        float4 xv = xr[k4];
        int kb = k4 * 4;
#pragma unroll
        for (int f = 0; f < F_HID; f++) {
            acc[f] = fmaf(xv.x, sW[(kb + 0) * F_HID + f], acc[f]);
            acc[f] = fmaf(xv.y, sW[(kb + 1) * F_HID + f], acc[f]);
            acc[f] = fmaf(xv.z, sW[(kb + 2) * F_HID + f], acc[f]);
            acc[f] = fmaf(xv.w, sW[(kb + 3) * F_HID + f], acc[f]);
        }
    }

    float4* h1o = reinterpret_cast<float4*>(g_h1 + (size_t)node * F_HID);
#pragma unroll
    for (int q = 0; q < F_HID / 4; q++)
        h1o[q] = make_float4(acc[q*4+0], acc[q*4+1], acc[q*4+2], acc[q*4+3]);
}

// ---------------------------------------------------------------------------
// layer-1 gather: 4 lanes per node, lane q owns features [4q,4q+4) as float4.
// agg1 = h1[n]*dinv^2 + sum h1[row]*norm;  epilogue: r1 = relu(agg1 + b1)
// ---------------------------------------------------------------------------
__global__ void k_gather0(const float* __restrict__ b1) {
    int t = blockIdx.x * blockDim.x + threadIdx.x;
    int node = t >> 2;
    int q    = t & 3;
    if (node >= N_NODES) return;

    const float4* src = reinterpret_cast<const float4*>(g_h1);
    float di = g_dinv[node];
    float s  = di * di;
    float4 acc = src[node * 4 + q];
    acc.x *= s; acc.y *= s; acc.z *= s; acc.w *= s;

    int start = g_ptr[node];
    int end   = g_ptr[node + 1];
#pragma unroll 2
    for (int i = start; i < end; i++) {
        int2 e = g_sedge[i];                      // broadcast across 4 lanes
        float nm = __int_as_float(e.y);
        float4 v = src[e.x * 4 + q];
        acc.x = fmaf(v.x, nm, acc.x);
        acc.y = fmaf(v.y, nm, acc.y);
        acc.z = fmaf(v.z, nm, acc.z);
        acc.w = fmaf(v.w, nm, acc.w);
    }

    float4 bf = reinterpret_cast<const float4*>(b1)[q];
    float4 r;
    r.x = fmaxf(acc.x + bf.x, 0.0f);
    r.y = fmaxf(acc.y + bf.y, 0.0f);
    r.z = fmaxf(acc.z + bf.z, 0.0f);
    r.w = fmaxf(acc.w + bf.w, 0.0f);
    reinterpret_cast<float4*>(g_r1)[node * 4 + q] = r;
}

// ---------------------------------------------------------------------------
// layer-2 gather fused with projection + log_softmax.
// 4 lanes per node; after the gather, lane q handles output cols {4j+q}.
// ---------------------------------------------------------------------------
__global__ void k_gather1_final(const float* __restrict__ W2,
                                const float* __restrict__ b2,
                                float* __restrict__ out) {
    __shared__ float sW[F_HID * F_OUT];
    __shared__ float sb[F_OUT];
    for (int i = threadIdx.x; i < F_HID * F_OUT; i += blockDim.x) sW[i] = W2[i];
    for (int i = threadIdx.x; i < F_OUT; i += blockDim.x) sb[i] = b2[i];
    __syncthreads();

    int t = blockIdx.x * blockDim.x + threadIdx.x;
    int node = t >> 2;
    int q    = t & 3;
    if (node >= N_NODES) return;

    const float4* src = reinterpret_cast<const float4*>(g_r1);
    float di = g_dinv[node];
    float s  = di * di;
    float4 acc = src[node * 4 + q];
    acc.x *= s; acc.y *= s; acc.z *= s; acc.w *= s;

    int start = g_ptr[node];
    int end   = g_ptr[node + 1];
#pragma unroll 2
    for (int i = start; i < end; i++) {
        int2 e = g_sedge[i];
        float nm = __int_as_float(e.y);
        float4 v = src[e.x * 4 + q];
        acc.x = fmaf(v.x, nm, acc.x);
        acc.y = fmaf(v.y, nm, acc.y);
        acc.z = fmaf(v.z, nm, acc.z);
        acc.w = fmaf(v.w, nm, acc.w);
    }
    // acc = agg2 features [4q, 4q+4) of this node

    // projection: lane q -> output cols c = 4j + q, j = 0..9
    float z[10];
#pragma unroll
    for (int j = 0; j < 10; j++) z[j] = sb[4 * j + q];

#pragma unroll
    for (int sl = 0; sl < 4; sl++) {
        float ax = __shfl_sync(0xffffffffu, acc.x, sl, 4);
        float ay = __shfl_sync(0xffffffffu, acc.y, sl, 4);
        float az = __shfl_sync(0xffffffffu, acc.z, sl, 4);
        float aw = __shfl_sync(0xffffffffu, acc.w, sl, 4);
        int k0 = 4 * sl;
#pragma unroll
        for (int j = 0; j < 10; j++) {
            int c = 4 * j + q;
            z[j] = fmaf(ax, sW[(k0 + 0) * F_OUT + c], z[j]);
            z[j] = fmaf(ay, sW[(k0 + 1) * F_OUT + c], z[j]);
            z[j] = fmaf(az, sW[(k0 + 2) * F_OUT + c], z[j]);
            z[j] = fmaf(aw, sW[(k0 + 3) * F_OUT + c], z[j]);
        }
    }

    // log_softmax over 40 cols (width-4 reductions)
    float m = z[0];
#pragma unroll
    for (int j = 1; j < 10; j++) m = fmaxf(m, z[j]);
    m = fmaxf(m, __shfl_xor_sync(0xffffffffu, m, 1, 4));
    m = fmaxf(m, __shfl_xor_sync(0xffffffffu, m, 2, 4));

    float se = 0.0f;
#pragma unroll
    for (int j = 0; j < 10; j++) se += expf(z[j] - m);
    se += __shfl_xor_sync(0xffffffffu, se, 1, 4);
    se += __shfl_xor_sync(0xffffffffu, se, 2, 4);
    float lse = m + logf(se);

    float* op = out + (size_t)node * F_OUT;
#pragma unroll
    for (int j = 0; j < 10; j++) op[4 * j + q] = z[j] - lse;
}

// ---------------------------------------------------------------------------
// launch — 4 kernels total
// ---------------------------------------------------------------------------
extern "C" void kernel_launch(void* const* d_in, const int* in_sizes, int n_in,
                              void* d_out, int out_size) {
    const float* x  = nullptr;
    const void*  ei = nullptr;
    const float* ew = nullptr;
    const float* W1 = nullptr;
    const float* b1 = nullptr;
    const float* W2 = nullptr;
    const float* b2 = nullptr;

    for (int i = 0; i < n_in; i++) {
        switch (in_sizes[i]) {
            case N_NODES * F_IN:   x  = (const float*)d_in[i]; break;
            case 2 * E_EDGES:      ei = d_in[i];               break;
            case E_EDGES:          ew = (const float*)d_in[i]; break;
            case F_IN * F_HID:     W1 = (const float*)d_in[i]; break;
            case F_HID:            b1 = (const float*)d_in[i]; break;
            case F_HID * F_OUT:    W2 = (const float*)d_in[i]; break;
            case F_OUT:            b2 = (const float*)d_in[i]; break;
            default: break;
        }
    }
    float* out = (float*)d_out;

    const int GT = (N_NODES * 4 + 255) / 256;

    k_prep<<<PREP_BLOCKS, PREP_THREADS>>>(ei, ew);
    k_gemm1<<<(N_NODES + 127) / 128, 128>>>(x, W1);
    k_gather0<<<GT, 256>>>(b1);
    k_gather1_final<<<GT, 256>>>(W2, b2, out);
}

// round 14
// speedup vs baseline: 1.1423x; 1.0843x over previous
#include <cuda_runtime.h>
#include <cuda_bf16.h>
#include <math.h>

#define N_NODES 100000
#define E_EDGES 3200000
#define F_IN    256
#define F_HID   16
#define F_OUT   40

#define SCAN_BS 1024
#define SCAN_NB ((N_NODES + SCAN_BS - 1) / SCAN_BS)   // 98

#define NPB   64      // nodes per gather block (256 threads / 4 lanes)
#define CHUNK 2048    // smem edge-stage capacity (16 KB)

// -------- scratch (static device globals; 16B-aligned) ----------------------
__device__ __align__(16) float g_deg   [N_NODES];
__device__ __align__(16) float g_dinv  [N_NODES];
__device__ __align__(16) float g_h1    [N_NODES * F_HID];
__device__ __align__(16) float g_r1    [N_NODES * F_HID];
__device__ __align__(16) int2  g_rc    [E_EDGES];      // {row, col}
__device__ __align__(16) int   g_cnt   [N_NODES];
__device__ __align__(16) int   g_ptr   [N_NODES + 1];
__device__ __align__(16) int   g_cursor[N_NODES];
__device__ __align__(16) int2  g_sedge [E_EDGES];      // {row, bits(norm)} sorted by col
__device__ __align__(16) int   g_bsum  [SCAN_NB];
__device__ __align__(16) int   g_boff  [SCAN_NB];
__device__ int g_idx32 = 0;   // 1 => edge_index is int32, 0 => int64

// ---------------------------------------------------------------------------
// 0. detect edge_index dtype
// ---------------------------------------------------------------------------
__global__ void k_detect(const long long* __restrict__ ei) {
    __shared__ int s_or[16];
    int bad = 0;
#pragma unroll
    for (int q = 0; q < 8; q++) {
        long long v = ei[threadIdx.x + q * 512];
        if (v < 0 || v >= N_NODES) bad = 1;
    }
    bad = __any_sync(0xffffffffu, bad) ? 1 : 0;
    if ((threadIdx.x & 31) == 0) s_or[threadIdx.x >> 5] = bad;
    __syncthreads();
    if (threadIdx.x == 0) {
        int r = 0;
        for (int w = 0; w < 16; w++) r |= s_or[w];
        g_idx32 = r;
    }
}

// ---------------------------------------------------------------------------
// 1. node init
// ---------------------------------------------------------------------------
__global__ void k_init() {
    int i = blockIdx.x * blockDim.x + threadIdx.x;
    if (i < N_NODES) { g_deg[i] = 1.0f; g_cnt[i] = 0; }
}

// ---------------------------------------------------------------------------
// 2. edge decode + degree/count histogram
// ---------------------------------------------------------------------------
__global__ void k_edges(const void* __restrict__ ei,
                        const float* __restrict__ ew) {
    int e = blockIdx.x * blockDim.x + threadIdx.x;
    if (e >= E_EDGES) return;
    int row, col;
    if (g_idx32) {
        row = ((const int*)ei)[e];
        col = ((const int*)ei)[E_EDGES + e];
    } else {
        row = (int)((const long long*)ei)[e];
        col = (int)((const long long*)ei)[E_EDGES + e];
    }
    if ((unsigned)row >= (unsigned)N_NODES) row = 0;
    if ((unsigned)col >= (unsigned)N_NODES) col = 0;
    g_rc[e] = make_int2(row, col);
    atomicAdd(&g_deg[col], ew[e]);
    atomicAdd(&g_cnt[col], 1);
}

// ---------------------------------------------------------------------------
// 3. per-chunk exclusive scan of cnt + dinv
// ---------------------------------------------------------------------------
__global__ void k_scan_block() {
    __shared__ int s[SCAN_BS];
    int i = blockIdx.x * SCAN_BS + threadIdx.x;
    int v = (i < N_NODES) ? g_cnt[i] : 0;
    s[threadIdx.x] = v;
    // dinv fused here (deg is final)
    if (i < N_NODES) {
        float d = g_deg[i];
        g_dinv[i] = (d > 0.0f) ? rsqrtf(d) : 0.0f;
    }
    __syncthreads();
#pragma unroll
    for (int off = 1; off < SCAN_BS; off <<= 1) {
        int t = (threadIdx.x >= off) ? s[threadIdx.x - off] : 0;
        __syncthreads();
        s[threadIdx.x] += t;
        __syncthreads();
    }
    if (i < N_NODES) g_ptr[i] = s[threadIdx.x] - v;   // exclusive within chunk
    if (threadIdx.x == SCAN_BS - 1) g_bsum[blockIdx.x] = s[SCAN_BS - 1];
}

__global__ void k_scan_bsum() {
    if (threadIdx.x == 0) {
        int run = 0;
        for (int b = 0; b < SCAN_NB; b++) {
            g_boff[b] = run;
            run += g_bsum[b];
        }
    }
}

__global__ void k_scan_add() {
    int i = blockIdx.x * blockDim.x + threadIdx.x;
    if (i < N_NODES) {
        int p = g_ptr[i] + g_boff[i >> 10];
        g_ptr[i] = p;
        g_cursor[i] = p;
    }
    if (i == 0) g_ptr[N_NODES] = E_EDGES;
}

// ---------------------------------------------------------------------------
// 4. CSR fill: packed (row, norm), bucketed by col
// ---------------------------------------------------------------------------
__global__ void k_fill(const float* __restrict__ ew) {
    int e = blockIdx.x * blockDim.x + threadIdx.x;
    if (e >= E_EDGES) return;
    int2 rc = g_rc[e];
    float norm = g_dinv[rc.x] * ew[e] * g_dinv[rc.y];
    int pos = atomicAdd(&g_cursor[rc.y], 1);
    g_sedge[pos] = make_int2(rc.x, __float_as_int(norm));
}

// ---------------------------------------------------------------------------
// 5. h1 = x @ W1 (thread-per-node, W1 in smem)
// ---------------------------------------------------------------------------
__global__ void k_gemm1(const float* __restrict__ x,
                        const float* __restrict__ W1) {
    __shared__ float sW[F_IN * F_HID];   // 16 KB
    for (int i = threadIdx.x; i < F_IN * F_HID; i += blockDim.x)
        sW[i] = W1[i];
    __syncthreads();

    int node = blockIdx.x * blockDim.x + threadIdx.x;
    if (node >= N_NODES) return;

    float acc[F_HID];
#pragma unroll
    for (int f = 0; f < F_HID; f++) acc[f] = 0.0f;

    const float4* xr = reinterpret_cast<const float4*>(x + (size_t)node * F_IN);
#pragma unroll 4
    for (int k4 = 0; k4 < F_IN / 4; k4++) {
        float4 xv = xr[k4];
        int kb = k4 * 4;
#pragma unroll
        for (int f = 0; f < F_HID; f++) {
            acc[f] = fmaf(xv.x, sW[(kb + 0) * F_HID + f], acc[f]);
            acc[f] = fmaf(xv.y, sW[(kb + 1) * F_HID + f], acc[f]);
            acc[f] = fmaf(xv.z, sW[(kb + 2) * F_HID + f], acc[f]);
            acc[f] = fmaf(xv.w, sW[(kb + 3) * F_HID + f], acc[f]);
        }
    }

    float4* h1o = reinterpret_cast<float4*>(g_h1 + (size_t)node * F_HID);
#pragma unroll
    for (int q = 0; q < F_HID / 4; q++)
        h1o[q] = make_float4(acc[q*4+0], acc[q*4+1], acc[q*4+2], acc[q*4+3]);
}

// ---------------------------------------------------------------------------
// gather core: 4 lanes per node (lane q owns features [4q,4q+4) as float4);
// block owns NPB consecutive nodes whose CSR windows form one contiguous
// g_sedge range -> cooperatively staged through smem (coalesced 128B loads,
// LDS broadcast consumption).
// ---------------------------------------------------------------------------
template <int LAYER>
__device__ __forceinline__ void gather_body(float4& acc, int node) {
    __shared__ int2 s_edges[CHUNK];

    const int q = threadIdx.x & 3;
    const float4* src = reinterpret_cast<const float4*>(LAYER == 0 ? g_h1 : g_r1);

    int node_base = blockIdx.x * NPB;
    int last = min(node_base + NPB, N_NODES);

    int my_start = 0, my_end = 0;
    if (node < N_NODES) {
        my_start = g_ptr[node];
        my_end   = g_ptr[node + 1];
    }
    int blk_start = g_ptr[node_base];
    int blk_end   = g_ptr[last];

    for (int chunk = blk_start; chunk < blk_end; chunk += CHUNK) {
        int n = min(CHUNK, blk_end - chunk);
        __syncthreads();
        for (int i = threadIdx.x; i < n; i += blockDim.x)
            s_edges[i] = g_sedge[chunk + i];
        __syncthreads();

        int lo = max(my_start, chunk);
        int hi = min(my_end, chunk + n);
#pragma unroll 4
        for (int i = lo; i < hi; i++) {
            int2 e = s_edges[i - chunk];
            float nm = __int_as_float(e.y);
            float4 v = src[e.x * 4 + q];
            acc.x = fmaf(v.x, nm, acc.x);
            acc.y = fmaf(v.y, nm, acc.y);
            acc.z = fmaf(v.z, nm, acc.z);
            acc.w = fmaf(v.w, nm, acc.w);
        }
    }
}

// layer-1: agg1 = h1[n]*dinv^2 + sum h1[row]*norm ; r1 = relu(agg1 + b1)
__global__ void k_gather0(const float* __restrict__ b1) {
    int t = blockIdx.x * blockDim.x + threadIdx.x;
    int node = t >> 2;
    int q    = t & 3;

    float4 acc = make_float4(0, 0, 0, 0);
    if (node < N_NODES) {
        float di = g_dinv[node];
        float s  = di * di;
        acc = reinterpret_cast<const float4*>(g_h1)[node * 4 + q];
        acc.x *= s; acc.y *= s; acc.z *= s; acc.w *= s;
    }

    gather_body<0>(acc, node);

    if (node < N_NODES) {
        float4 bf = reinterpret_cast<const float4*>(b1)[q];
        float4 r;
        r.x = fmaxf(acc.x + bf.x, 0.0f);
        r.y = fmaxf(acc.y + bf.y, 0.0f);
        r.z = fmaxf(acc.z + bf.z, 0.0f);
        r.w = fmaxf(acc.w + bf.w, 0.0f);
        reinterpret_cast<float4*>(g_r1)[node * 4 + q] = r;
    }
}

// layer-2 gather + projection + log_softmax, direct store to out
__global__ void k_gather1_final(const float* __restrict__ W2,
                                const float* __restrict__ b2,
                                float* __restrict__ out) {
    __shared__ float sW[F_HID * F_OUT];
    __shared__ float sb[F_OUT];
    for (int i = threadIdx.x; i < F_HID * F_OUT; i += blockDim.x) sW[i] = W2[i];
    for (int i = threadIdx.x; i < F_OUT; i += blockDim.x) sb[i] = b2[i];

    int t = blockIdx.x * blockDim.x + threadIdx.x;
    int node = t >> 2;
    int q    = t & 3;

    float4 acc = make_float4(0, 0, 0, 0);
    if (node < N_NODES) {
        float di = g_dinv[node];
        float s  = di * di;
        acc = reinterpret_cast<const float4*>(g_r1)[node * 4 + q];
        acc.x *= s; acc.y *= s; acc.z *= s; acc.w *= s;
    }

    gather_body<1>(acc, node);   // includes __syncthreads: sW/sb ready after

    if (node >= N_NODES) return;

    // projection: lane q -> output cols c = 4j + q, j = 0..9
    float z[10];
#pragma unroll
    for (int j = 0; j < 10; j++) z[j] = sb[4 * j + q];

#pragma unroll
    for (int sl = 0; sl < 4; sl++) {
        float ax = __shfl_sync(0xffffffffu, acc.x, sl, 4);
        float ay = __shfl_sync(0xffffffffu, acc.y, sl, 4);
        float az = __shfl_sync(0xffffffffu, acc.z, sl, 4);
        float aw = __shfl_sync(0xffffffffu, acc.w, sl, 4);
        int k0 = 4 * sl;
#pragma unroll
        for (int j = 0; j < 10; j++) {
            int c = 4 * j + q;
            z[j] = fmaf(ax, sW[(k0 + 0) * F_OUT + c], z[j]);
            z[j] = fmaf(ay, sW[(k0 + 1) * F_OUT + c], z[j]);
            z[j] = fmaf(az, sW[(k0 + 2) * F_OUT + c], z[j]);
            z[j] = fmaf(aw, sW[(k0 + 3) * F_OUT + c], z[j]);
        }
    }

    // log_softmax over 40 cols (width-4 reductions)
    float m = z[0];
#pragma unroll
    for (int j = 1; j < 10; j++) m = fmaxf(m, z[j]);
    m = fmaxf(m, __shfl_xor_sync(0xffffffffu, m, 1, 4));
    m = fmaxf(m, __shfl_xor_sync(0xffffffffu, m, 2, 4));

    float se = 0.0f;
#pragma unroll
    for (int j = 0; j < 10; j++) se += expf(z[j] - m);
    se += __shfl_xor_sync(0xffffffffu, se, 1, 4);
    se += __shfl_xor_sync(0xffffffffu, se, 2, 4);
    float lse = m + logf(se);

    float* op = out + (size_t)node * F_OUT;
#pragma unroll
    for (int j = 0; j < 10; j++) op[4 * j + q] = z[j] - lse;
}

// ---------------------------------------------------------------------------
// launch
// ---------------------------------------------------------------------------
extern "C" void kernel_launch(void* const* d_in, const int* in_sizes, int n_in,
                              void* d_out, int out_size) {
    const float* x  = nullptr;
    const void*  ei = nullptr;
    const float* ew = nullptr;
    const float* W1 = nullptr;
    const float* b1 = nullptr;
    const float* W2 = nullptr;
    const float* b2 = nullptr;

    for (int i = 0; i < n_in; i++) {
        switch (in_sizes[i]) {
            case N_NODES * F_IN:   x  = (const float*)d_in[i]; break;
            case 2 * E_EDGES:      ei = d_in[i];               break;
            case E_EDGES:          ew = (const float*)d_in[i]; break;
            case F_IN * F_HID:     W1 = (const float*)d_in[i]; break;
            case F_HID:            b1 = (const float*)d_in[i]; break;
            case F_HID * F_OUT:    W2 = (const float*)d_in[i]; break;
            case F_OUT:            b2 = (const float*)d_in[i]; break;
            default: break;
        }
    }
    float* out = (float*)d_out;

    const int T  = 256;
    const int GE = (E_EDGES + T - 1) / T;
    const int GN = (N_NODES + T - 1) / T;
    const int GG = (N_NODES + NPB - 1) / NPB;

    k_detect<<<1, 512>>>((const long long*)ei);
    k_init<<<GN, T>>>();
    k_edges<<<GE, T>>>(ei, ew);
    k_scan_block<<<SCAN_NB, SCAN_BS>>>();
    k_scan_bsum<<<1, 32>>>();
    k_scan_add<<<GN, T>>>();
    k_fill<<<GE, T>>>(ew);

    k_gemm1<<<(N_NODES + 127) / 128, 128>>>(x, W1);
    k_gather0<<<GG, T>>>(b1);
    k_gather1_final<<<GG, T>>>(W2, b2, out);
}

// round 15
// speedup vs baseline: 1.2764x; 1.1174x over previous
#include <cuda_runtime.h>
#include <cuda_bf16.h>
#include <math.h>

#define N_NODES 100000
#define E_EDGES 3200000
#define F_IN    256
#define F_HID   16
#define F_OUT   40

#define SCAN_BS 1024
#define SCAN_NB ((N_NODES + SCAN_BS - 1) / SCAN_BS)   // 98

#define NPB   64      // nodes per gather block (256 threads / 4 lanes)
#define CHUNK 2048    // smem edge-stage capacity (16 KB)

#define GEMM_BLOCKS ((N_NODES + 255) / 256)           // 391
#define EDGE_BLOCKS ((E_EDGES + 255) / 256)           // 12500

// -------- scratch (static device globals; 16B-aligned) ----------------------
__device__ __align__(16) float g_deg   [N_NODES];
__device__ __align__(16) float g_dinv  [N_NODES];
__device__ __align__(16) float g_h1    [N_NODES * F_HID];
__device__ __align__(16) float g_r1    [N_NODES * F_HID];
__device__ __align__(16) int2  g_rc    [E_EDGES];      // {row, col}
__device__ __align__(16) int   g_cnt   [N_NODES];
__device__ __align__(16) int   g_ptr   [N_NODES + 1];
__device__ __align__(16) int   g_cursor[N_NODES];
__device__ __align__(16) int2  g_sedge [E_EDGES];      // {row, bits(norm)} sorted by col
__device__ __align__(16) int   g_bsum  [SCAN_NB];
__device__ int g_idx32 = 0;   // 1 => edge_index is int32, 0 => int64

// ---------------------------------------------------------------------------
// 1. node init; block 0 additionally detects edge_index dtype
// ---------------------------------------------------------------------------
__global__ void k_init_detect(const long long* __restrict__ ei) {
    int i = blockIdx.x * blockDim.x + threadIdx.x;
    if (i < N_NODES) { g_deg[i] = 1.0f; g_cnt[i] = 0; }

    if (blockIdx.x == 0) {
        __shared__ int s_or[8];
        int bad = 0;
#pragma unroll
        for (int q = 0; q < 16; q++) {
            long long v = ei[threadIdx.x + q * 256];
            if (v < 0 || v >= N_NODES) bad = 1;
        }
        bad = __any_sync(0xffffffffu, bad) ? 1 : 0;
        if ((threadIdx.x & 31) == 0) s_or[threadIdx.x >> 5] = bad;
        __syncthreads();
        if (threadIdx.x == 0) {
            int r = 0;
            for (int w = 0; w < 8; w++) r |= s_or[w];
            g_idx32 = r;
        }
    }
}

// ---------------------------------------------------------------------------
// 2. merged kernel: blocks [0, GEMM_BLOCKS) -> h1 = x @ W1
//                   blocks [GEMM_BLOCKS, +EDGE_BLOCKS) -> edge decode + hist
//    (independent work; merging gives DRAM-phase overlap without streams)
// ---------------------------------------------------------------------------
__global__ void __launch_bounds__(256)
k_edges_gemm(const void* __restrict__ ei, const float* __restrict__ ew,
             const float* __restrict__ x, const float* __restrict__ W1) {
    __shared__ float sW[F_IN * F_HID];   // 16 KB (gemm blocks only)

    if (blockIdx.x < GEMM_BLOCKS) {
        // ---------------- GEMM part ----------------
        for (int i = threadIdx.x; i < F_IN * F_HID; i += blockDim.x)
            sW[i] = W1[i];
        __syncthreads();

        int node = blockIdx.x * 256 + threadIdx.x;
        if (node >= N_NODES) return;

        float acc[F_HID];
#pragma unroll
        for (int f = 0; f < F_HID; f++) acc[f] = 0.0f;

        const float4* xr = reinterpret_cast<const float4*>(x + (size_t)node * F_IN);
#pragma unroll 4
        for (int k4 = 0; k4 < F_IN / 4; k4++) {
            float4 xv = xr[k4];
            int kb = k4 * 4;
#pragma unroll
            for (int f = 0; f < F_HID; f++) {
                acc[f] = fmaf(xv.x, sW[(kb + 0) * F_HID + f], acc[f]);
                acc[f] = fmaf(xv.y, sW[(kb + 1) * F_HID + f], acc[f]);
                acc[f] = fmaf(xv.z, sW[(kb + 2) * F_HID + f], acc[f]);
                acc[f] = fmaf(xv.w, sW[(kb + 3) * F_HID + f], acc[f]);
            }
        }

        float4* h1o = reinterpret_cast<float4*>(g_h1 + (size_t)node * F_HID);
#pragma unroll
        for (int q = 0; q < F_HID / 4; q++)
            h1o[q] = make_float4(acc[q*4+0], acc[q*4+1], acc[q*4+2], acc[q*4+3]);
    } else {
        // ---------------- edge part ----------------
        int e = (blockIdx.x - GEMM_BLOCKS) * 256 + threadIdx.x;
        if (e >= E_EDGES) return;
        int row, col;
        if (g_idx32) {
            row = ((const int*)ei)[e];
            col = ((const int*)ei)[E_EDGES + e];
        } else {
            row = (int)((const long long*)ei)[e];
            col = (int)((const long long*)ei)[E_EDGES + e];
        }
        if ((unsigned)row >= (unsigned)N_NODES) row = 0;
        if ((unsigned)col >= (unsigned)N_NODES) col = 0;
        g_rc[e] = make_int2(row, col);
        atomicAdd(&g_deg[col], ew[e]);
        atomicAdd(&g_cnt[col], 1);
    }
}

// ---------------------------------------------------------------------------
// 3. per-chunk exclusive scan of cnt (warp-shuffle) + dinv
// ---------------------------------------------------------------------------
__global__ void __launch_bounds__(SCAN_BS)
k_scan_block() {
    __shared__ int ws[32];
    const unsigned FULL = 0xffffffffu;
    int tid  = threadIdx.x;
    int lane = tid & 31, wid = tid >> 5;
    int i = blockIdx.x * SCAN_BS + tid;

    int v = (i < N_NODES) ? g_cnt[i] : 0;

    if (i < N_NODES) {                 // dinv fused (deg is final)
        float d = g_deg[i];
        g_dinv[i] = (d > 0.0f) ? rsqrtf(d) : 0.0f;
    }

    int xv = v;
#pragma unroll
    for (int o = 1; o < 32; o <<= 1) {
        int t = __shfl_up_sync(FULL, xv, o);
        if (lane >= o) xv += t;
    }
    if (lane == 31) ws[wid] = xv;
    __syncthreads();
    if (wid == 0) {
        int y = ws[lane];
#pragma unroll
        for (int o = 1; o < 32; o <<= 1) {
            int t = __shfl_up_sync(FULL, y, o);
            if (lane >= o) y += t;
        }
        ws[lane] = y;
    }
    __syncthreads();
    int incl = xv + (wid > 0 ? ws[wid - 1] : 0);
    if (i < N_NODES) g_ptr[i] = incl - v;           // exclusive within chunk
    if (tid == SCAN_BS - 1) g_bsum[blockIdx.x] = incl;
}

// ---------------------------------------------------------------------------
// 4. add chunk offsets (each block redundantly scans the 98 chunk sums)
// ---------------------------------------------------------------------------
__global__ void k_scan_add() {
    __shared__ int sb[128];
    int tid = threadIdx.x;
    if (tid < 128) sb[tid] = (tid < SCAN_NB) ? g_bsum[tid] : 0;
    __syncthreads();
#pragma unroll
    for (int o = 1; o < 128; o <<= 1) {
        int t = (tid < 128 && tid >= o) ? sb[tid - o] : 0;
        __syncthreads();
        if (tid < 128) sb[tid] += t;
        __syncthreads();
    }
    // sb now inclusive; exclusive offset for chunk c is sb[c-1]
    int i = blockIdx.x * blockDim.x + tid;
    if (i < N_NODES) {
        int c = i >> 10;
        int p = g_ptr[i] + (c > 0 ? sb[c - 1] : 0);
        g_ptr[i] = p;
        g_cursor[i] = p;
    }
    if (i == 0) g_ptr[N_NODES] = E_EDGES;
}

// ---------------------------------------------------------------------------
// 5. CSR fill: packed (row, norm), bucketed by col
// ---------------------------------------------------------------------------
__global__ void k_fill(const float* __restrict__ ew) {
    int e = blockIdx.x * blockDim.x + threadIdx.x;
    if (e >= E_EDGES) return;
    int2 rc = g_rc[e];
    float norm = g_dinv[rc.x] * ew[e] * g_dinv[rc.y];
    int pos = atomicAdd(&g_cursor[rc.y], 1);
    g_sedge[pos] = make_int2(rc.x, __float_as_int(norm));
}

// ---------------------------------------------------------------------------
// gather core: 4 lanes per node (lane q owns features [4q,4q+4) as float4);
// block owns NPB consecutive nodes; their contiguous g_sedge range is staged
// through smem (coalesced 128B loads, LDS broadcast consumption).
// ---------------------------------------------------------------------------
template <int LAYER>
__device__ __forceinline__ void gather_body(float4& acc, int node) {
    __shared__ int2 s_edges[CHUNK];

    const int q = threadIdx.x & 3;
    const float4* src = reinterpret_cast<const float4*>(LAYER == 0 ? g_h1 : g_r1);

    int node_base = blockIdx.x * NPB;
    int last = min(node_base + NPB, N_NODES);

    int my_start = 0, my_end = 0;
    if (node < N_NODES) {
        my_start = g_ptr[node];
        my_end   = g_ptr[node + 1];
    }
    int blk_start = g_ptr[node_base];
    int blk_end   = g_ptr[last];

    for (int chunk = blk_start; chunk < blk_end; chunk += CHUNK) {
        int n = min(CHUNK, blk_end - chunk);
        __syncthreads();
        for (int i = threadIdx.x; i < n; i += blockDim.x)
            s_edges[i] = g_sedge[chunk + i];
        __syncthreads();

        int lo = max(my_start, chunk);
        int hi = min(my_end, chunk + n);
#pragma unroll 4
        for (int i = lo; i < hi; i++) {
            int2 e = s_edges[i - chunk];
            float nm = __int_as_float(e.y);
            float4 v = src[e.x * 4 + q];
            acc.x = fmaf(v.x, nm, acc.x);
            acc.y = fmaf(v.y, nm, acc.y);
            acc.z = fmaf(v.z, nm, acc.z);
            acc.w = fmaf(v.w, nm, acc.w);
        }
    }
}

// layer-1: agg1 = h1[n]*dinv^2 + sum h1[row]*norm ; r1 = relu(agg1 + b1)
__global__ void k_gather0(const float* __restrict__ b1) {
    int t = blockIdx.x * blockDim.x + threadIdx.x;
    int node = t >> 2;
    int q    = t & 3;

    float4 acc = make_float4(0, 0, 0, 0);
    if (node < N_NODES) {
        float di = g_dinv[node];
        float s  = di * di;
        acc = reinterpret_cast<const float4*>(g_h1)[node * 4 + q];
        acc.x *= s; acc.y *= s; acc.z *= s; acc.w *= s;
    }

    gather_body<0>(acc, node);

    if (node < N_NODES) {
        float4 bf = reinterpret_cast<const float4*>(b1)[q];
        float4 r;
        r.x = fmaxf(acc.x + bf.x, 0.0f);
        r.y = fmaxf(acc.y + bf.y, 0.0f);
        r.z = fmaxf(acc.z + bf.z, 0.0f);
        r.w = fmaxf(acc.w + bf.w, 0.0f);
        reinterpret_cast<float4*>(g_r1)[node * 4 + q] = r;
    }
}

// layer-2 gather + projection + log_softmax, direct store to out
__global__ void k_gather1_final(const float* __restrict__ W2,
                                const float* __restrict__ b2,
                                float* __restrict__ out) {
    __shared__ float sW[F_HID * F_OUT];
    __shared__ float sb[F_OUT];
    for (int i = threadIdx.x; i < F_HID * F_OUT; i += blockDim.x) sW[i] = W2[i];
    for (int i = threadIdx.x; i < F_OUT; i += blockDim.x) sb[i] = b2[i];

    int t = blockIdx.x * blockDim.x + threadIdx.x;
    int node = t >> 2;
    int q    = t & 3;

    float4 acc = make_float4(0, 0, 0, 0);
    if (node < N_NODES) {
        float di = g_dinv[node];
        float s  = di * di;
        acc = reinterpret_cast<const float4*>(g_r1)[node * 4 + q];
        acc.x *= s; acc.y *= s; acc.z *= s; acc.w *= s;
    }

    gather_body<1>(acc, node);   // includes __syncthreads: sW/sb ready after

    if (node >= N_NODES) return;

    // projection: lane q -> output cols c = 4j + q, j = 0..9
    float z[10];
#pragma unroll
    for (int j = 0; j < 10; j++) z[j] = sb[4 * j + q];

#pragma unroll
    for (int sl = 0; sl < 4; sl++) {
        float ax = __shfl_sync(0xffffffffu, acc.x, sl, 4);
        float ay = __shfl_sync(0xffffffffu, acc.y, sl, 4);
        float az = __shfl_sync(0xffffffffu, acc.z, sl, 4);
        float aw = __shfl_sync(0xffffffffu, acc.w, sl, 4);
        int k0 = 4 * sl;
#pragma unroll
        for (int j = 0; j < 10; j++) {
            int c = 4 * j + q;
            z[j] = fmaf(ax, sW[(k0 + 0) * F_OUT + c], z[j]);
            z[j] = fmaf(ay, sW[(k0 + 1) * F_OUT + c], z[j]);
            z[j] = fmaf(az, sW[(k0 + 2) * F_OUT + c], z[j]);
            z[j] = fmaf(aw, sW[(k0 + 3) * F_OUT + c], z[j]);
        }
    }

    // log_softmax over 40 cols (width-4 reductions)
    float m = z[0];
#pragma unroll
    for (int j = 1; j < 10; j++) m = fmaxf(m, z[j]);
    m = fmaxf(m, __shfl_xor_sync(0xffffffffu, m, 1, 4));
    m = fmaxf(m, __shfl_xor_sync(0xffffffffu, m, 2, 4));

    float se = 0.0f;
#pragma unroll
    for (int j = 0; j < 10; j++) se += expf(z[j] - m);
    se += __shfl_xor_sync(0xffffffffu, se, 1, 4);
    se += __shfl_xor_sync(0xffffffffu, se, 2, 4);
    float lse = m + logf(se);

    float* op = out + (size_t)node * F_OUT;
#pragma unroll
    for (int j = 0; j < 10; j++) op[4 * j + q] = z[j] - lse;
}

// ---------------------------------------------------------------------------
// launch — 7 kernels
// ---------------------------------------------------------------------------
extern "C" void kernel_launch(void* const* d_in, const int* in_sizes, int n_in,
                              void* d_out, int out_size) {
    const float* x  = nullptr;
    const void*  ei = nullptr;
    const float* ew = nullptr;
    const float* W1 = nullptr;
    const float* b1 = nullptr;
    const float* W2 = nullptr;
    const float* b2 = nullptr;

    for (int i = 0; i < n_in; i++) {
        switch (in_sizes[i]) {
            case N_NODES * F_IN:   x  = (const float*)d_in[i]; break;
            case 2 * E_EDGES:      ei = d_in[i];               break;
            case E_EDGES:          ew = (const float*)d_in[i]; break;
            case F_IN * F_HID:     W1 = (const float*)d_in[i]; break;
            case F_HID:            b1 = (const float*)d_in[i]; break;
            case F_HID * F_OUT:    W2 = (const float*)d_in[i]; break;
            case F_OUT:            b2 = (const float*)d_in[i]; break;
            default: break;
        }
    }
    float* out = (float*)d_out;

    const int T  = 256;
    const int GE = (E_EDGES + T - 1) / T;
    const int GN = (N_NODES + T - 1) / T;
    const int GG = (N_NODES + NPB - 1) / NPB;

    k_init_detect<<<GN, T>>>((const long long*)ei);
    k_edges_gemm<<<GEMM_BLOCKS + EDGE_BLOCKS, T>>>(ei, ew, x, W1);
    k_scan_block<<<SCAN_NB, SCAN_BS>>>();
    k_scan_add<<<GN, T>>>();
    k_fill<<<GE, T>>>(ew);
    k_gather0<<<GG, T>>>(b1);
    k_gather1_final<<<GG, T>>>(W2, b2, out);
}

// round 16
// speedup vs baseline: 1.3691x; 1.0726x over previous
#include <cuda_runtime.h>
#include <cuda_bf16.h>
#include <cuda_fp16.h>
#include <math.h>

#define N_NODES 100000
#define E_EDGES 3200000
#define F_IN    256
#define F_HID   16
#define F_OUT   40

#define SCAN_BS 1024
#define SCAN_NB ((N_NODES + SCAN_BS - 1) / SCAN_BS)   // 98

#define NPB   64      // nodes per gather block (256 threads / 4 lanes)
#define CHUNK 2048    // smem edge-stage capacity (16 KB)

#define GEMM_BLOCKS ((N_NODES + 255) / 256)           // 391
#define EDGE_BLOCKS ((E_EDGES + 255) / 256)           // 12500

// -------- scratch (static device globals; 16B-aligned) ----------------------
__device__ __align__(16) float  g_deg   [N_NODES];
__device__ __align__(16) float  g_dinv  [N_NODES];
__device__ __align__(16) __half g_h1s   [N_NODES * F_HID];  // h1 * dinv (fp16)
__device__ __align__(16) __half g_r1s   [N_NODES * F_HID];  // relu(agg1+b1)*dinv
__device__ __align__(16) int2   g_rc    [E_EDGES];          // {row, col}
__device__ __align__(16) int    g_cnt   [N_NODES];
__device__ __align__(16) int    g_ptr   [N_NODES + 1];
__device__ __align__(16) int    g_cursor[N_NODES];
__device__ __align__(16) int2   g_sedge [E_EDGES];          // {row, bits(w)} sorted by col
__device__ __align__(16) int    g_bsum  [SCAN_NB];
__device__ int g_idx32 = 0;   // 1 => edge_index is int32, 0 => int64

// ---------------------------------------------------------------------------
// 1. node init; block 0 additionally detects edge_index dtype
// ---------------------------------------------------------------------------
__global__ void k_init_detect(const long long* __restrict__ ei) {
    int i = blockIdx.x * blockDim.x + threadIdx.x;
    if (i < N_NODES) { g_deg[i] = 1.0f; g_cnt[i] = 0; }

    if (blockIdx.x == 0) {
        __shared__ int s_or[8];
        int bad = 0;
#pragma unroll
        for (int q = 0; q < 16; q++) {
            long long v = ei[threadIdx.x + q * 256];
            if (v < 0 || v >= N_NODES) bad = 1;
        }
        bad = __any_sync(0xffffffffu, bad) ? 1 : 0;
        if ((threadIdx.x & 31) == 0) s_or[threadIdx.x >> 5] = bad;
        __syncthreads();
        if (threadIdx.x == 0) {
            int r = 0;
            for (int w = 0; w < 8; w++) r |= s_or[w];
            g_idx32 = r;
        }
    }
}

// ---------------------------------------------------------------------------
// 2. merged kernel: blocks [0, GEMM_BLOCKS) -> h1 = x @ W1 (fp32 acc)
//    NOTE: h1s store needs dinv, which isn't ready yet -> store fp32 acc
//    temporarily into g_sedge (reused as scratch: 25.6 MB >= 6.4 MB needed).
//    blocks [GEMM_BLOCKS, ...) -> edge decode + histograms.
// ---------------------------------------------------------------------------
__global__ void __launch_bounds__(256)
k_edges_gemm(const void* __restrict__ ei, const float* __restrict__ ew,
             const float* __restrict__ x, const float* __restrict__ W1) {
    __shared__ float sW[F_IN * F_HID];   // 16 KB (gemm blocks only)

    if (blockIdx.x < GEMM_BLOCKS) {
        for (int i = threadIdx.x; i < F_IN * F_HID; i += blockDim.x)
            sW[i] = W1[i];
        __syncthreads();

        int node = blockIdx.x * 256 + threadIdx.x;
        if (node >= N_NODES) return;

        float acc[F_HID];
#pragma unroll
        for (int f = 0; f < F_HID; f++) acc[f] = 0.0f;

        const float4* xr = reinterpret_cast<const float4*>(x + (size_t)node * F_IN);
#pragma unroll 4
        for (int k4 = 0; k4 < F_IN / 4; k4++) {
            float4 xv = xr[k4];
            int kb = k4 * 4;
#pragma unroll
            for (int f = 0; f < F_HID; f++) {
                acc[f] = fmaf(xv.x, sW[(kb + 0) * F_HID + f], acc[f]);
                acc[f] = fmaf(xv.y, sW[(kb + 1) * F_HID + f], acc[f]);
                acc[f] = fmaf(xv.z, sW[(kb + 2) * F_HID + f], acc[f]);
                acc[f] = fmaf(xv.w, sW[(kb + 3) * F_HID + f], acc[f]);
            }
        }

        // fp32 h1 scratch (g_sedge reused; overwritten later by k_fill)
        float4* h1o = reinterpret_cast<float4*>(g_sedge) + (size_t)node * 4;
#pragma unroll
        for (int q = 0; q < F_HID / 4; q++)
            h1o[q] = make_float4(acc[q*4+0], acc[q*4+1], acc[q*4+2], acc[q*4+3]);
    } else {
        int e = (blockIdx.x - GEMM_BLOCKS) * 256 + threadIdx.x;
        if (e >= E_EDGES) return;
        int row, col;
        if (g_idx32) {
            row = ((const int*)ei)[e];
            col = ((const int*)ei)[E_EDGES + e];
        } else {
            row = (int)((const long long*)ei)[e];
            col = (int)((const long long*)ei)[E_EDGES + e];
        }
        if ((unsigned)row >= (unsigned)N_NODES) row = 0;
        if ((unsigned)col >= (unsigned)N_NODES) col = 0;
        g_rc[e] = make_int2(row, col);
        atomicAdd(&g_deg[col], ew[e]);
        atomicAdd(&g_cnt[col], 1);
    }
}

// ---------------------------------------------------------------------------
// 3. per-chunk exclusive scan of cnt (warp-shuffle) + dinv + h1s=h1*dinv (fp16)
// ---------------------------------------------------------------------------
__global__ void __launch_bounds__(SCAN_BS)
k_scan_block() {
    __shared__ int ws[32];
    const unsigned FULL = 0xffffffffu;
    int tid  = threadIdx.x;
    int lane = tid & 31, wid = tid >> 5;
    int i = blockIdx.x * SCAN_BS + tid;

    int v = (i < N_NODES) ? g_cnt[i] : 0;

    if (i < N_NODES) {
        float d = g_deg[i];
        float di = (d > 0.0f) ? rsqrtf(d) : 0.0f;
        g_dinv[i] = di;
        // convert fp32 h1 scratch -> fp16 h1s with dinv scaling
        const float4* h1i = reinterpret_cast<const float4*>(g_sedge) + (size_t)i * 4;
        uint2* ho = reinterpret_cast<uint2*>(g_h1s) + (size_t)i * 4;
#pragma unroll
        for (int q = 0; q < 4; q++) {
            float4 hv = h1i[q];
            __half2 lo = __floats2half2_rn(hv.x * di, hv.y * di);
            __half2 hi = __floats2half2_rn(hv.z * di, hv.w * di);
            uint2 pk;
            pk.x = *reinterpret_cast<unsigned*>(&lo);
            pk.y = *reinterpret_cast<unsigned*>(&hi);
            ho[q] = pk;
        }
    }

    int xv = v;
#pragma unroll
    for (int o = 1; o < 32; o <<= 1) {
        int t = __shfl_up_sync(FULL, xv, o);
        if (lane >= o) xv += t;
    }
    if (lane == 31) ws[wid] = xv;
    __syncthreads();
    if (wid == 0) {
        int y = ws[lane];
#pragma unroll
        for (int o = 1; o < 32; o <<= 1) {
            int t = __shfl_up_sync(FULL, y, o);
            if (lane >= o) y += t;
        }
        ws[lane] = y;
    }
    __syncthreads();
    int incl = xv + (wid > 0 ? ws[wid - 1] : 0);
    if (i < N_NODES) g_ptr[i] = incl - v;
    if (tid == SCAN_BS - 1) g_bsum[blockIdx.x] = incl;
}

// ---------------------------------------------------------------------------
// 4. add chunk offsets (each block redundantly scans the 98 chunk sums)
// ---------------------------------------------------------------------------
__global__ void k_scan_add() {
    __shared__ int sb[128];
    int tid = threadIdx.x;
    if (tid < 128) sb[tid] = (tid < SCAN_NB) ? g_bsum[tid] : 0;
    __syncthreads();
#pragma unroll
    for (int o = 1; o < 128; o <<= 1) {
        int t = (tid < 128 && tid >= o) ? sb[tid - o] : 0;
        __syncthreads();
        if (tid < 128) sb[tid] += t;
        __syncthreads();
    }
    int i = blockIdx.x * blockDim.x + tid;
    if (i < N_NODES) {
        int c = i >> 10;
        int p = g_ptr[i] + (c > 0 ? sb[c - 1] : 0);
        g_ptr[i] = p;
        g_cursor[i] = p;
    }
    if (i == 0) g_ptr[N_NODES] = E_EDGES;
}

// ---------------------------------------------------------------------------
// 5. CSR fill: packed (row, raw w), bucketed by col — no dinv needed
// ---------------------------------------------------------------------------
__global__ void k_fill(const float* __restrict__ ew) {
    int e = blockIdx.x * blockDim.x + threadIdx.x;
    if (e >= E_EDGES) return;
    int2 rc = g_rc[e];
    int pos = atomicAdd(&g_cursor[rc.y], 1);
    g_sedge[pos] = make_int2(rc.x, __float_as_int(ew[e]));
}

// ---------------------------------------------------------------------------
// gather core: 4 lanes per node; lane q owns features [4q,4q+4).
// fp16 source (8B per lane per edge), fp32 accumulation.
// acc_out = src[n] + sum_e w_e * src[row_e]   (all values pre-scaled by dinv)
// ---------------------------------------------------------------------------
template <int LAYER>
__device__ __forceinline__ void gather_body(float4& acc, int node) {
    __shared__ int2 s_edges[CHUNK];

    const int q = threadIdx.x & 3;
    const uint2* src = reinterpret_cast<const uint2*>(LAYER == 0 ? g_h1s : g_r1s);

    int node_base = blockIdx.x * NPB;
    int last = min(node_base + NPB, N_NODES);

    int my_start = 0, my_end = 0;
    if (node < N_NODES) {
        my_start = g_ptr[node];
        my_end   = g_ptr[node + 1];
    }
    int blk_start = g_ptr[node_base];
    int blk_end   = g_ptr[last];

    for (int chunk = blk_start; chunk < blk_end; chunk += CHUNK) {
        int n = min(CHUNK, blk_end - chunk);
        __syncthreads();
        for (int i = threadIdx.x; i < n; i += blockDim.x)
            s_edges[i] = g_sedge[chunk + i];
        __syncthreads();

        int lo = max(my_start, chunk);
        int hi = min(my_end, chunk + n);
#pragma unroll 4
        for (int i = lo; i < hi; i++) {
            int2 e = s_edges[i - chunk];
            float w = __int_as_float(e.y);
            uint2 pk = src[e.x * 4 + q];
            __half2 h0 = *reinterpret_cast<__half2*>(&pk.x);
            __half2 h1 = *reinterpret_cast<__half2*>(&pk.y);
            float2 a = __half22float2(h0);
            float2 b = __half22float2(h1);
            acc.x = fmaf(a.x, w, acc.x);
            acc.y = fmaf(a.y, w, acc.y);
            acc.z = fmaf(b.x, w, acc.z);
            acc.w = fmaf(b.y, w, acc.w);
        }
    }
}

__device__ __forceinline__ float4 load_h4(const uint2* src, int node, int q) {
    uint2 pk = src[node * 4 + q];
    __half2 h0 = *reinterpret_cast<__half2*>(&pk.x);
    __half2 h1 = *reinterpret_cast<__half2*>(&pk.y);
    float2 a = __half22float2(h0);
    float2 b = __half22float2(h1);
    return make_float4(a.x, a.y, b.x, b.y);
}

// layer-1: acc = h1s[n] + sum w*h1s[row]; agg1 = dinv*acc;
// r1s = relu(agg1 + b1) * dinv  (fp16 store)
__global__ void k_gather0(const float* __restrict__ b1) {
    int t = blockIdx.x * blockDim.x + threadIdx.x;
    int node = t >> 2;
    int q    = t & 3;

    float4 acc = make_float4(0, 0, 0, 0);
    if (node < N_NODES)
        acc = load_h4(reinterpret_cast<const uint2*>(g_h1s), node, q);

    gather_body<0>(acc, node);

    if (node < N_NODES) {
        float di = g_dinv[node];
        float4 bf = reinterpret_cast<const float4*>(b1)[q];
        float rx = fmaxf(fmaf(acc.x, di, bf.x), 0.0f) * di;
        float ry = fmaxf(fmaf(acc.y, di, bf.y), 0.0f) * di;
        float rz = fmaxf(fmaf(acc.z, di, bf.z), 0.0f) * di;
        float rw = fmaxf(fmaf(acc.w, di, bf.w), 0.0f) * di;
        __half2 lo = __floats2half2_rn(rx, ry);
        __half2 hi = __floats2half2_rn(rz, rw);
        uint2 pk;
        pk.x = *reinterpret_cast<unsigned*>(&lo);
        pk.y = *reinterpret_cast<unsigned*>(&hi);
        reinterpret_cast<uint2*>(g_r1s)[node * 4 + q] = pk;
    }
}

// layer-2: acc = r1s[n] + sum w*r1s[row]; agg2 = dinv*acc;
// then projection + log_softmax, direct store
__global__ void k_gather1_final(const float* __restrict__ W2,
                                const float* __restrict__ b2,
                                float* __restrict__ out) {
    __shared__ float sW[F_HID * F_OUT];
    __shared__ float sb[F_OUT];
    for (int i = threadIdx.x; i < F_HID * F_OUT; i += blockDim.x) sW[i] = W2[i];
    for (int i = threadIdx.x; i < F_OUT; i += blockDim.x) sb[i] = b2[i];

    int t = blockIdx.x * blockDim.x + threadIdx.x;
    int node = t >> 2;
    int q    = t & 3;

    float4 acc = make_float4(0, 0, 0, 0);
    if (node < N_NODES)
        acc = load_h4(reinterpret_cast<const uint2*>(g_r1s), node, q);

    gather_body<1>(acc, node);   // includes __syncthreads: sW/sb ready after

    if (node >= N_NODES) return;

    float di = g_dinv[node];
    acc.x *= di; acc.y *= di; acc.z *= di; acc.w *= di;

    // projection: lane q -> output cols c = 4j + q, j = 0..9
    float z[10];
#pragma unroll
    for (int j = 0; j < 10; j++) z[j] = sb[4 * j + q];

#pragma unroll
    for (int sl = 0; sl < 4; sl++) {
        float ax = __shfl_sync(0xffffffffu, acc.x, sl, 4);
        float ay = __shfl_sync(0xffffffffu, acc.y, sl, 4);
        float az = __shfl_sync(0xffffffffu, acc.z, sl, 4);
        float aw = __shfl_sync(0xffffffffu, acc.w, sl, 4);
        int k0 = 4 * sl;
#pragma unroll
        for (int j = 0; j < 10; j++) {
            int c = 4 * j + q;
            z[j] = fmaf(ax, sW[(k0 + 0) * F_OUT + c], z[j]);
            z[j] = fmaf(ay, sW[(k0 + 1) * F_OUT + c], z[j]);
            z[j] = fmaf(az, sW[(k0 + 2) * F_OUT + c], z[j]);
            z[j] = fmaf(aw, sW[(k0 + 3) * F_OUT + c], z[j]);
        }
    }

    float m = z[0];
#pragma unroll
    for (int j = 1; j < 10; j++) m = fmaxf(m, z[j]);
    m = fmaxf(m, __shfl_xor_sync(0xffffffffu, m, 1, 4));
    m = fmaxf(m, __shfl_xor_sync(0xffffffffu, m, 2, 4));

    float se = 0.0f;
#pragma unroll
    for (int j = 0; j < 10; j++) se += expf(z[j] - m);
    se += __shfl_xor_sync(0xffffffffu, se, 1, 4);
    se += __shfl_xor_sync(0xffffffffu, se, 2, 4);
    float lse = m + logf(se);

    float* op = out + (size_t)node * F_OUT;
#pragma unroll
    for (int j = 0; j < 10; j++) op[4 * j + q] = z[j] - lse;
}

// ---------------------------------------------------------------------------
// launch — 7 kernels
// ---------------------------------------------------------------------------
extern "C" void kernel_launch(void* const* d_in, const int* in_sizes, int n_in,
                              void* d_out, int out_size) {
    const float* x  = nullptr;
    const void*  ei = nullptr;
    const float* ew = nullptr;
    const float* W1 = nullptr;
    const float* b1 = nullptr;
    const float* W2 = nullptr;
    const float* b2 = nullptr;

    for (int i = 0; i < n_in; i++) {
        switch (in_sizes[i]) {
            case N_NODES * F_IN:   x  = (const float*)d_in[i]; break;
            case 2 * E_EDGES:      ei = d_in[i];               break;
            case E_EDGES:          ew = (const float*)d_in[i]; break;
            case F_IN * F_HID:     W1 = (const float*)d_in[i]; break;
            case F_HID:            b1 = (const float*)d_in[i]; break;
            case F_HID * F_OUT:    W2 = (const float*)d_in[i]; break;
            case F_OUT:            b2 = (const float*)d_in[i]; break;
            default: break;
        }
    }
    float* out = (float*)d_out;

    const int T  = 256;
    const int GE = (E_EDGES + T - 1) / T;
    const int GN = (N_NODES + T - 1) / T;
    const int GG = (N_NODES + NPB - 1) / NPB;

    k_init_detect<<<GN, T>>>((const long long*)ei);
    k_edges_gemm<<<GEMM_BLOCKS + EDGE_BLOCKS, T>>>(ei, ew, x, W1);
    k_scan_block<<<SCAN_NB, SCAN_BS>>>();
    k_scan_add<<<GN, T>>>();
    k_fill<<<GE, T>>>(ew);
    k_gather0<<<GG, T>>>(b1);
    k_gather1_final<<<GG, T>>>(W2, b2, out);
}